// round 8
// baseline (speedup 1.0000x reference)
#include <cuda_runtime.h>

#define THREADS 256
#define PER 32                 // elements per thread
#define COLS 8192
#define NBINS 256
#define FBUF 128               // final candidate buffer (bin population)

// order-preserving float<->uint key (scalars only: fallback pivot generation)
__device__ __forceinline__ unsigned f2k(float f) {
    unsigned u = __float_as_uint(f);
    return (u & 0x80000000u) ? ~u : (u | 0x80000000u);
}
__device__ __forceinline__ float k2f(unsigned kk) {
    unsigned u = (kk & 0x80000000u) ? (kk ^ 0x80000000u) : ~kk;
    return __uint_as_float(u);
}

__global__ void __launch_bounds__(THREADS) rsoftmax_kernel(
    const float* __restrict__ in,
    const float* __restrict__ rate_p,
    float* __restrict__ out)
{
    __shared__ int      s_hist[NBINS];
    __shared__ int      s_cnt[8];
    __shared__ float    s_facc[8];
    __shared__ unsigned s_lo, s_hi;
    __shared__ int      s_clo, s_cle, s_done, s_m2, s_binb, s_rb, s_M;
    __shared__ float    s_T, s_inv;
    __shared__ float    s_fb[FBUF];

    const int tid  = threadIdx.x;
    const int lane = tid & 31;
    const int wid  = tid >> 5;
    const float* rp = in  + (size_t)blockIdx.x * COLS;
    float*       op = out + (size_t)blockIdx.x * COLS;

    // ---- rank from sparsity_rate (uniform) ----
    float r = fminf(fmaxf(rate_p[0], 0.0f), 1.0f);
    int idx = (int)(r * (float)COLS);        // trunc, matches astype(int32)
    if (idx > COLS - 1) idx = COLS - 1;      // jnp.take clamp semantics
    const int k = (COLS - 1) - idx;          // k-th smallest (0-indexed)

    // ---- analytic Gaussian bracket (prior only; exact fallback below) ----
    float q = ((float)k + 0.5f) / (float)COLS;
    q = fminf(fmaxf(q, 4.0e-5f), 1.0f - 4.0e-5f);
    float c   = normcdfinvf(q);
    float pdf = 0.3989423f * __expf(-0.5f * c * c);
    float hw  = 6.0f * sqrtf(q * (1.0f - q) * (1.0f / (float)COLS)) / pdf + 0.02f;
    const float A = c - hw, B = c + hw;
    const float scale = (float)NBINS / (B - A);
    const float sA = A * scale;              // t = x*scale - sA, monotone in x

    // ---- load row into registers (front-batched float4, max MLP) ----
    float x[PER];
#pragma unroll
    for (int j = 0; j < PER / 4; j++) {
        float4 v = ((const float4*)rp)[j * THREADS + tid];
        x[4*j+0] = v.x; x[4*j+1] = v.y; x[4*j+2] = v.z; x[4*j+3] = v.w;
    }

    s_hist[tid] = 0;                          // THREADS == NBINS
    if (tid == 0) { s_m2 = 0; s_done = 0; s_binb = -1; }
    __syncthreads();

    // ---- single pass: count(t>=0) + in-bracket histogram ----
    int cge = 0;                              // count of t >= 0  (x >= bracket lo)
#pragma unroll
    for (int j = 0; j < PER; j++) {
        float t = fmaf(x[j], scale, -sA);
        bool ge = (t >= 0.0f);
        cge += ge;
        if (ge && t < (float)NBINS)
            atomicAdd(&s_hist[(int)t], 1);
    }
#pragma unroll
    for (int o = 16; o; o >>= 1) cge += __shfl_down_sync(0xffffffffu, cge, o);
    if (lane == 0) s_cnt[wid] = cge;
    __syncthreads();
    int Clo = COLS;                           // count below bracket = N - count(t>=0)
#pragma unroll
    for (int w = 0; w < 8; w++) Clo -= s_cnt[w];
    const int rr = k - Clo;                   // rank within histogram

    // ---- warp 0: scan bins, locate target bin ----
    if (wid == 0) {
        int h[8]; int local = 0;
#pragma unroll
        for (int t2 = 0; t2 < 8; t2++) { h[t2] = s_hist[lane * 8 + t2]; local += h[t2]; }
        int incl = local;
#pragma unroll
        for (int o = 1; o < 32; o <<= 1) {
            int v = __shfl_up_sync(0xffffffffu, incl, o);
            if (lane >= o) incl += v;
        }
        int run = incl - local;               // exclusive prefix
        if (lane == 31) s_M = incl;           // total in-bracket count
#pragma unroll
        for (int t2 = 0; t2 < 8; t2++) {
            if (rr >= run && rr < run + h[t2]) { s_binb = lane * 8 + t2; s_rb = rr - run; }
            run += h[t2];
        }
    }
    __syncthreads();

    const int Mtot = s_M;
    const int binb = s_binb;
    const bool ok = (rr >= 0) && (rr < Mtot) && (binb >= 0) && (s_hist[binb] <= FBUF);
    float thresh;

    if (ok) {
        const int rb = s_rb;
        // ---- extract the few values in the target bin ----
#pragma unroll
        for (int j = 0; j < PER; j++) {
            float t = fmaf(x[j], scale, -sA);
            if (t >= 0.0f && (int)t == binb) {
                int pos = atomicAdd(&s_m2, 1);    // pos < FBUF guaranteed by hist
                s_fb[pos] = x[j];
            }
        }
        __syncthreads();
        int mm = s_m2;
        if (tid < mm) {
            float v = s_fb[tid];
            int less = 0, leq = 0;
            for (int j2 = 0; j2 < mm; j2++) {
                float u = s_fb[j2];
                less += (u < v); leq += (u <= v);
            }
            if (less <= rb && rb < leq) s_T = v;  // ties write the same value
        }
        __syncthreads();
        thresh = s_T;
    } else {
        // ---- fallback: exact full-range counting bisection over registers ----
        if (tid == 0) {
            s_lo = f2k(-3.4028235e38f); s_hi = f2k(3.4028235e38f);
            s_clo = 0; s_cle = COLS;
            if (s_lo >= s_hi) { s_done = 1; s_T = k2f(s_lo); }
        }
        __syncthreads();

        for (int iter = 0; iter < 96; iter++) {
            if (s_done) break;                    // uniform (post-barrier)
            unsigned lo = s_lo, hi = s_hi;
            int clo = s_clo, cle = s_cle, cw = cle - clo;
            if (cw <= 64) break;
            unsigned p;
            if (iter & 1) {                       // guaranteed-progress midpoint
                p = lo + ((hi - lo + 1u) >> 1);
            } else {                              // value-space interpolation
                float flo = k2f(lo), fhi = k2f(hi);
                float frac = ((float)(k - clo) + 0.5f) / (float)cw;
                p = f2k(flo + (fhi - flo) * frac);
                if (p <= lo) p = lo + 1u;
                if (p > hi)  p = hi;
            }
            float pf = k2f(p);
            int cnt = 0;
#pragma unroll
            for (int j = 0; j < PER; j++) cnt += (x[j] < pf);
#pragma unroll
            for (int o = 16; o; o >>= 1) cnt += __shfl_down_sync(0xffffffffu, cnt, o);
            if (lane == 0) s_cnt[wid] = cnt;
            __syncthreads();
            if (tid == 0) {
                int ct = 0;
#pragma unroll
                for (int w = 0; w < 8; w++) ct += s_cnt[w];
                if (ct > k) { s_hi = p - 1u; s_cle = ct; }
                else        { s_lo = p;      s_clo = ct; }
                if (s_lo >= s_hi) { s_done = 1; s_T = k2f(s_lo); }
            }
            __syncthreads();
        }

        if (!s_done) {                            // window <= 64 -> exact rank scan
            float flo = k2f(s_lo), fhi = k2f(s_hi);
            int rr2 = k - s_clo;
#pragma unroll
            for (int j = 0; j < PER; j++) {
                float v = x[j];
                if (v >= flo && v <= fhi) {
                    int pos = atomicAdd(&s_m2, 1);
                    if (pos < FBUF) s_fb[pos] = v;
                }
            }
            __syncthreads();
            int mm = min(s_m2, FBUF);
            if (tid < mm) {
                float v = s_fb[tid];
                int less = 0, leq = 0;
                for (int j2 = 0; j2 < mm; j2++) {
                    float u = s_fb[j2];
                    less += (u < v); leq += (u <= v);
                }
                if (less <= rr2 && rr2 < leq) s_T = v;
            }
            __syncthreads();
        }
        thresh = s_T;
    }

    // ---- epilogue: we = relu(x - thresh) * exp(x), normalize, store ----
    float acc = 0.0f;
#pragma unroll
    for (int j = 0; j < PER; j++) {
        float w  = fmaxf(x[j] - thresh, 0.0f);
        float we = w * __expf(x[j]);
        x[j] = we;
        acc += we;
    }
#pragma unroll
    for (int o = 16; o; o >>= 1) acc += __shfl_down_sync(0xffffffffu, acc, o);
    if (lane == 0) s_facc[wid] = acc;
    __syncthreads();
    if (tid == 0) {
        float s = 0.0f;
#pragma unroll
        for (int w = 0; w < 8; w++) s += s_facc[w];
        s_inv = 1.0f / s;
    }
    __syncthreads();
    const float inv = s_inv;

#pragma unroll
    for (int j = 0; j < PER / 4; j++) {
        float4 v;
        v.x = x[4*j+0] * inv;
        v.y = x[4*j+1] * inv;
        v.z = x[4*j+2] * inv;
        v.w = x[4*j+3] * inv;
        ((float4*)op)[j * THREADS + tid] = v;
    }
}

extern "C" void kernel_launch(void* const* d_in, const int* in_sizes, int n_in,
                              void* d_out, int out_size) {
    const float* in     = (const float*)d_in[0];
    const float* rate_p = (const float*)d_in[1];
    float*       out    = (float*)d_out;
    const int rows = in_sizes[0] / COLS;   // 8192
    rsoftmax_kernel<<<rows, THREADS>>>(in, rate_p, out);
}

// round 9
// speedup vs baseline: 1.2275x; 1.2275x over previous
#include <cuda_runtime.h>

#define THREADS 256
#define PER 32                 // elements per thread
#define COLS 8192
#define NBINS 256
#define FBUF 128               // final candidate buffer (bin population)

// order-preserving float<->uint key (scalars only: fallback pivot generation)
__device__ __forceinline__ unsigned f2k(float f) {
    unsigned u = __float_as_uint(f);
    return (u & 0x80000000u) ? ~u : (u | 0x80000000u);
}
__device__ __forceinline__ float k2f(unsigned kk) {
    unsigned u = (kk & 0x80000000u) ? (kk ^ 0x80000000u) : ~kk;
    return __uint_as_float(u);
}

__global__ void __launch_bounds__(THREADS, 4) rsoftmax_kernel(
    const float* __restrict__ in,
    const float* __restrict__ rate_p,
    float* __restrict__ out)
{
    __shared__ int      s_hist[NBINS];
    __shared__ int      s_cnt[8];
    __shared__ float    s_facc[8];
    __shared__ unsigned s_lo, s_hi;
    __shared__ int      s_clo, s_cle, s_done, s_m2, s_binb, s_rb, s_M;
    __shared__ float    s_T, s_inv;
    __shared__ float    s_fb[FBUF];

    const int tid  = threadIdx.x;
    const int lane = tid & 31;
    const int wid  = tid >> 5;
    const float* rp = in  + (size_t)blockIdx.x * COLS;
    float*       op = out + (size_t)blockIdx.x * COLS;

    // ---- rank from sparsity_rate (uniform) ----
    float r = fminf(fmaxf(rate_p[0], 0.0f), 1.0f);
    int idx = (int)(r * (float)COLS);        // trunc, matches astype(int32)
    if (idx > COLS - 1) idx = COLS - 1;      // jnp.take clamp semantics
    const int k = (COLS - 1) - idx;          // k-th smallest (0-indexed)

    // ---- analytic Gaussian bracket (prior only; exact fallback below) ----
    float q = ((float)k + 0.5f) / (float)COLS;
    q = fminf(fmaxf(q, 4.0e-5f), 1.0f - 4.0e-5f);
    float c   = normcdfinvf(q);
    float pdf = 0.3989423f * __expf(-0.5f * c * c);
    float hw  = 6.0f * sqrtf(q * (1.0f - q) * (1.0f / (float)COLS)) / pdf + 0.02f;
    const float A = c - hw, B = c + hw;
    const float scale = (float)NBINS / (B - A);
    const float sA = A * scale;              // t = x*scale - sA, monotone in x

    // ---- load row into registers (front-batched float4, max MLP) ----
    float x[PER];
#pragma unroll
    for (int j = 0; j < PER / 4; j++) {
        float4 v = ((const float4*)rp)[j * THREADS + tid];
        x[4*j+0] = v.x; x[4*j+1] = v.y; x[4*j+2] = v.z; x[4*j+3] = v.w;
    }

    s_hist[tid] = 0;                          // THREADS == NBINS
    if (tid == 0) { s_m2 = 0; s_done = 0; s_binb = -1; }
    __syncthreads();

    // ---- single pass: count(t>=0) + in-bracket histogram ----
    // partial unroll: limits live temporaries (R8's full unroll blew regs to 110)
    int cge = 0;                              // count of t >= 0  (x >= bracket lo)
#pragma unroll 8
    for (int j = 0; j < PER; j++) {
        float t = fmaf(x[j], scale, -sA);
        bool ge = (t >= 0.0f);
        cge += ge;
        if (ge && t < (float)NBINS)
            atomicAdd(&s_hist[(int)t], 1);
    }
#pragma unroll
    for (int o = 16; o; o >>= 1) cge += __shfl_down_sync(0xffffffffu, cge, o);
    if (lane == 0) s_cnt[wid] = cge;
    __syncthreads();
    int Clo = COLS;                           // count below bracket = N - count(t>=0)
#pragma unroll
    for (int w = 0; w < 8; w++) Clo -= s_cnt[w];
    const int rr = k - Clo;                   // rank within histogram

    // ---- warp 0: scan bins, locate target bin ----
    if (wid == 0) {
        int h[8]; int local = 0;
#pragma unroll
        for (int t2 = 0; t2 < 8; t2++) { h[t2] = s_hist[lane * 8 + t2]; local += h[t2]; }
        int incl = local;
#pragma unroll
        for (int o = 1; o < 32; o <<= 1) {
            int v = __shfl_up_sync(0xffffffffu, incl, o);
            if (lane >= o) incl += v;
        }
        int run = incl - local;               // exclusive prefix
        if (lane == 31) s_M = incl;           // total in-bracket count
#pragma unroll
        for (int t2 = 0; t2 < 8; t2++) {
            if (rr >= run && rr < run + h[t2]) { s_binb = lane * 8 + t2; s_rb = rr - run; }
            run += h[t2];
        }
    }
    __syncthreads();

    const int Mtot = s_M;
    const int binb = s_binb;
    const bool ok = (rr >= 0) && (rr < Mtot) && (binb >= 0) && (s_hist[binb] <= FBUF);
    float thresh;

    if (ok) {
        const int rb = s_rb;
        // ---- extract the few values in the target bin ----
#pragma unroll 8
        for (int j = 0; j < PER; j++) {
            float t = fmaf(x[j], scale, -sA);
            if (t >= 0.0f && (int)t == binb) {
                int pos = atomicAdd(&s_m2, 1);    // pos < FBUF guaranteed by hist
                s_fb[pos] = x[j];
            }
        }
        __syncthreads();
        int mm = s_m2;
        if (tid < mm) {
            float v = s_fb[tid];
            int less = 0, leq = 0;
            for (int j2 = 0; j2 < mm; j2++) {
                float u = s_fb[j2];
                less += (u < v); leq += (u <= v);
            }
            if (less <= rb && rb < leq) s_T = v;  // ties write the same value
        }
        __syncthreads();
        thresh = s_T;
    } else {
        // ---- fallback: exact full-range counting bisection over registers ----
        if (tid == 0) {
            s_lo = f2k(-3.4028235e38f); s_hi = f2k(3.4028235e38f);
            s_clo = 0; s_cle = COLS;
            if (s_lo >= s_hi) { s_done = 1; s_T = k2f(s_lo); }
        }
        __syncthreads();

        for (int iter = 0; iter < 96; iter++) {
            if (s_done) break;                    // uniform (post-barrier)
            unsigned lo = s_lo, hi = s_hi;
            int clo = s_clo, cle = s_cle, cw = cle - clo;
            if (cw <= 64) break;
            unsigned p;
            if (iter & 1) {                       // guaranteed-progress midpoint
                p = lo + ((hi - lo + 1u) >> 1);
            } else {                              // value-space interpolation
                float flo = k2f(lo), fhi = k2f(hi);
                float frac = ((float)(k - clo) + 0.5f) / (float)cw;
                p = f2k(flo + (fhi - flo) * frac);
                if (p <= lo) p = lo + 1u;
                if (p > hi)  p = hi;
            }
            float pf = k2f(p);
            int cnt = 0;
#pragma unroll 8
            for (int j = 0; j < PER; j++) cnt += (x[j] < pf);
#pragma unroll
            for (int o = 16; o; o >>= 1) cnt += __shfl_down_sync(0xffffffffu, cnt, o);
            if (lane == 0) s_cnt[wid] = cnt;
            __syncthreads();
            if (tid == 0) {
                int ct = 0;
#pragma unroll
                for (int w = 0; w < 8; w++) ct += s_cnt[w];
                if (ct > k) { s_hi = p - 1u; s_cle = ct; }
                else        { s_lo = p;      s_clo = ct; }
                if (s_lo >= s_hi) { s_done = 1; s_T = k2f(s_lo); }
            }
            __syncthreads();
        }

        if (!s_done) {                            // window <= 64 -> exact rank scan
            float flo = k2f(s_lo), fhi = k2f(s_hi);
            int rr2 = k - s_clo;
#pragma unroll 8
            for (int j = 0; j < PER; j++) {
                float v = x[j];
                if (v >= flo && v <= fhi) {
                    int pos = atomicAdd(&s_m2, 1);
                    if (pos < FBUF) s_fb[pos] = v;
                }
            }
            __syncthreads();
            int mm = min(s_m2, FBUF);
            if (tid < mm) {
                float v = s_fb[tid];
                int less = 0, leq = 0;
                for (int j2 = 0; j2 < mm; j2++) {
                    float u = s_fb[j2];
                    less += (u < v); leq += (u <= v);
                }
                if (less <= rr2 && rr2 < leq) s_T = v;
            }
            __syncthreads();
        }
        thresh = s_T;
    }

    // ---- epilogue: we = relu(x - thresh) * exp(x), normalize, store ----
    float acc = 0.0f;
#pragma unroll
    for (int j = 0; j < PER; j++) {
        float w  = fmaxf(x[j] - thresh, 0.0f);
        float we = w * __expf(x[j]);
        x[j] = we;
        acc += we;
    }
#pragma unroll
    for (int o = 16; o; o >>= 1) acc += __shfl_down_sync(0xffffffffu, acc, o);
    if (lane == 0) s_facc[wid] = acc;
    __syncthreads();
    if (tid == 0) {
        float s = 0.0f;
#pragma unroll
        for (int w = 0; w < 8; w++) s += s_facc[w];
        s_inv = 1.0f / s;
    }
    __syncthreads();
    const float inv = s_inv;

#pragma unroll
    for (int j = 0; j < PER / 4; j++) {
        float4 v;
        v.x = x[4*j+0] * inv;
        v.y = x[4*j+1] * inv;
        v.z = x[4*j+2] * inv;
        v.w = x[4*j+3] * inv;
        ((float4*)op)[j * THREADS + tid] = v;
    }
}

extern "C" void kernel_launch(void* const* d_in, const int* in_sizes, int n_in,
                              void* d_out, int out_size) {
    const float* in     = (const float*)d_in[0];
    const float* rate_p = (const float*)d_in[1];
    float*       out    = (float*)d_out;
    const int rows = in_sizes[0] / COLS;   // 8192
    rsoftmax_kernel<<<rows, THREADS>>>(in, rate_p, out);
}